// round 1
// baseline (speedup 1.0000x reference)
#include <cuda_runtime.h>
#include <cuda_bf16.h>
#include <math.h>

#define BATCH 256
#define TWOB 512
#define DIM 2048
#define HW 64
#define INV_TEMP 10.0f
#define BN_EPS 1e-5f
#define COS_EPS 1e-8f
#define SLICE_RANGE 2

typedef __nv_bfloat16 bf16;

// ---- scratch (device globals: no allocations allowed) ----
__device__ bf16  g_pb[TWOB * DIM];        // pooled, bf16
__device__ bf16  g_W1b[DIM * DIM];
__device__ bf16  g_W2b[DIM * DIM];
__device__ float g_h[TWOB * DIM];         // GEMM1 out (pre-BN)
__device__ float g_mu[DIM];
__device__ float g_istd[DIM];
__device__ bf16  g_hb[TWOB * DIM];        // BN+ReLU, bf16
__device__ float g_z[TWOB * DIM];         // GEMM2 out
__device__ bf16  g_znb[TWOB * DIM];       // normalized rows, bf16
__device__ float g_sim[BATCH * TWOB];     // similarity (rows 0..255 x all 512)
__device__ float g_lossb[BATCH];
__device__ float g_cntd[BATCH];

// ---------------------------------------------------------------------------
// 1) spatial mean pool: z[b,d,:,:] (64 contiguous f32) -> bf16 p[b,d]
//    one warp per (b,d); lane loads float2 -> fully coalesced 256B per warp
// ---------------------------------------------------------------------------
__global__ void pool_kernel(const float* __restrict__ z0,
                            const float* __restrict__ z1) {
    int gw   = (blockIdx.x * blockDim.x + threadIdx.x) >> 5;  // 0 .. TWOB*DIM-1
    int lane = threadIdx.x & 31;
    const float* src = (gw < BATCH * DIM)
                         ? z0 + (size_t)gw * HW
                         : z1 + (size_t)(gw - BATCH * DIM) * HW;
    float2 v = ((const float2*)src)[lane];
    float s = v.x + v.y;
#pragma unroll
    for (int o = 16; o > 0; o >>= 1) s += __shfl_xor_sync(0xffffffffu, s, o);
    if (lane == 0) g_pb[gw] = __float2bfloat16(s * (1.0f / 64.0f));
}

// ---------------------------------------------------------------------------
// 2) weights f32 -> bf16
// ---------------------------------------------------------------------------
__global__ void cvt_kernel(const float* __restrict__ W1,
                           const float* __restrict__ W2) {
    const int NPER = DIM * DIM / 4;  // float4 groups per matrix
    int i = blockIdx.x * blockDim.x + threadIdx.x;
    const float* src;
    bf16* dst;
    int j;
    if (i < NPER) { src = W1; dst = g_W1b; j = i; }
    else          { src = W2; dst = g_W2b; j = i - NPER; }
    float4 v = ((const float4*)src)[j];
    __nv_bfloat162 lo = __floats2bfloat162_rn(v.x, v.y);
    __nv_bfloat162 hi = __floats2bfloat162_rn(v.z, v.w);
    ((__nv_bfloat162*)dst)[j * 2]     = lo;
    ((__nv_bfloat162*)dst)[j * 2 + 1] = hi;
}

// ---------------------------------------------------------------------------
// 3) bf16 GEMM via mma.sync.m16n8k16 (HMMA), fp32 accumulate.
//    C[M,N] = A[M,K] * B[N,K]^T (+ bias), A/B row-major K-contiguous.
//    Block tile 128x64, 8 warps (4x2), warp tile 32x32 (2 m-tiles x 4 n-tiles).
//    smem stride 24 bf16 (48B = 12 banks) -> conflict-free fragment loads.
// ---------------------------------------------------------------------------
#define BM 128
#define BN 64
#define BK 16
#define SPAD 24

__global__ void __launch_bounds__(256, 2) gemm_kernel(
    const bf16* __restrict__ A, const bf16* __restrict__ Bm,
    float* __restrict__ C, const float* __restrict__ bias,
    int M, int N, int K) {
    __shared__ bf16 As[BM * SPAD];
    __shared__ bf16 Bs[BN * SPAD];
    const int tid  = threadIdx.x;
    const int warp = tid >> 5;
    const int lane = tid & 31;
    const int wm = warp >> 1;   // 0..3
    const int wn = warp & 1;    // 0..1
    const int g  = lane >> 2;   // 0..7
    const int t4 = lane & 3;    // 0..3
    const int rowBase = blockIdx.y * BM;
    const int colBase = blockIdx.x * BN;

    const int arow  = tid >> 1;          // 0..127
    const int ahalf = (tid & 1) * 8;     // 0 or 8
    const int brow  = (tid & 127) >> 1;  // 0..63

    float acc[2][4][4];
#pragma unroll
    for (int i = 0; i < 2; i++)
#pragma unroll
        for (int j = 0; j < 4; j++)
#pragma unroll
            for (int k = 0; k < 4; k++) acc[i][j][k] = 0.f;

    const bf16* aptr = A + (size_t)(rowBase + arow) * K + ahalf;
    const bf16* bptr = Bm + (size_t)(colBase + brow) * K + ahalf;

    for (int k0 = 0; k0 < K; k0 += BK) {
        *(uint4*)&As[arow * SPAD + ahalf] = *(const uint4*)(aptr + k0);
        if (tid < 128)
            *(uint4*)&Bs[brow * SPAD + ahalf] = *(const uint4*)(bptr + k0);
        __syncthreads();

        unsigned afr[2][4], bfr[4][2];
#pragma unroll
        for (int mt = 0; mt < 2; mt++) {
            int r = wm * 32 + mt * 16 + g;
            afr[mt][0] = *(const unsigned*)&As[r * SPAD + t4 * 2];
            afr[mt][1] = *(const unsigned*)&As[(r + 8) * SPAD + t4 * 2];
            afr[mt][2] = *(const unsigned*)&As[r * SPAD + t4 * 2 + 8];
            afr[mt][3] = *(const unsigned*)&As[(r + 8) * SPAD + t4 * 2 + 8];
        }
#pragma unroll
        for (int nt = 0; nt < 4; nt++) {
            int n = wn * 32 + nt * 8 + g;
            bfr[nt][0] = *(const unsigned*)&Bs[n * SPAD + t4 * 2];
            bfr[nt][1] = *(const unsigned*)&Bs[n * SPAD + t4 * 2 + 8];
        }
#pragma unroll
        for (int mt = 0; mt < 2; mt++)
#pragma unroll
            for (int nt = 0; nt < 4; nt++) {
                asm volatile(
                    "mma.sync.aligned.m16n8k16.row.col.f32.bf16.bf16.f32 "
                    "{%0,%1,%2,%3}, {%4,%5,%6,%7}, {%8,%9}, {%0,%1,%2,%3};\n"
                    : "+f"(acc[mt][nt][0]), "+f"(acc[mt][nt][1]),
                      "+f"(acc[mt][nt][2]), "+f"(acc[mt][nt][3])
                    : "r"(afr[mt][0]), "r"(afr[mt][1]),
                      "r"(afr[mt][2]), "r"(afr[mt][3]),
                      "r"(bfr[nt][0]), "r"(bfr[nt][1]));
            }
        __syncthreads();
    }

#pragma unroll
    for (int mt = 0; mt < 2; mt++) {
        int r0 = rowBase + wm * 32 + mt * 16 + g;
#pragma unroll
        for (int nt = 0; nt < 4; nt++) {
            int c0 = colBase + wn * 32 + nt * 8 + t4 * 2;
            float bx = bias ? bias[c0] : 0.f;
            float by = bias ? bias[c0 + 1] : 0.f;
            *(float2*)&C[(size_t)r0 * N + c0] =
                make_float2(acc[mt][nt][0] + bx, acc[mt][nt][1] + by);
            *(float2*)&C[(size_t)(r0 + 8) * N + c0] =
                make_float2(acc[mt][nt][2] + bx, acc[mt][nt][3] + by);
        }
    }
}

// ---------------------------------------------------------------------------
// 4) BatchNorm stats over batch (512 rows) per column
// ---------------------------------------------------------------------------
__global__ void bn_stats_kernel() {
    __shared__ float ss[8][32];
    __shared__ float sq[8][32];
    int tx = threadIdx.x & 31, ty = threadIdx.x >> 5;
    int col = blockIdx.x * 32 + tx;
    float s = 0.f, q = 0.f;
    for (int r = ty; r < TWOB; r += 8) {
        float v = g_h[(size_t)r * DIM + col];
        s += v; q += v * v;
    }
    ss[ty][tx] = s; sq[ty][tx] = q;
    __syncthreads();
    if (ty == 0) {
#pragma unroll
        for (int k = 1; k < 8; k++) { s += ss[k][tx]; q += sq[k][tx]; }
        float mu  = s * (1.f / TWOB);
        float var = q * (1.f / TWOB) - mu * mu;
        g_mu[col]   = mu;
        g_istd[col] = rsqrtf(var + BN_EPS);
    }
}

// ---------------------------------------------------------------------------
// 5) BN apply + ReLU -> bf16
// ---------------------------------------------------------------------------
__global__ void bn_apply_kernel(const float* __restrict__ gamma,
                                const float* __restrict__ beta) {
    int i = blockIdx.x * blockDim.x + threadIdx.x;
    int d = i & (DIM - 1);
    float v = (g_h[i] - g_mu[d]) * g_istd[d] * gamma[d] + beta[d];
    g_hb[i] = __float2bfloat16(fmaxf(v, 0.f));
}

// ---------------------------------------------------------------------------
// 6) row L2 normalize -> bf16
// ---------------------------------------------------------------------------
__global__ void rownorm_kernel() {
    __shared__ float red[256];
    int r = blockIdx.x, tid = threadIdx.x;
    const float* row = g_z + (size_t)r * DIM;
    float s = 0.f;
    for (int d = tid; d < DIM; d += 256) { float v = row[d]; s += v * v; }
    red[tid] = s;
    __syncthreads();
    for (int o = 128; o > 0; o >>= 1) {
        if (tid < o) red[tid] += red[tid + o];
        __syncthreads();
    }
    float inv = 1.f / fmaxf(sqrtf(red[0]), COS_EPS);
    for (int d = tid; d < DIM; d += 256)
        g_znb[(size_t)r * DIM + d] = __float2bfloat16(row[d] * inv);
}

// ---------------------------------------------------------------------------
// 7) per-row contrastive loss; block i handles sim row i (512 columns)
// ---------------------------------------------------------------------------
__global__ void loss_rows_kernel(const int* __restrict__ rel) {
    __shared__ float red[256];
    int i = blockIdx.x, j = threadIdx.x;
    int ri = rel[i];
    int rj = rel[j];
    float s1 = g_sim[i * TWOB + j];
    float e1 = expf(s1 * INV_TEMP);
    float e2 = expf(g_sim[i * TWOB + BATCH + j] * INV_TEMP);
    int diff = ri - rj; if (diff < 0) diff = -diff;
    bool isneg = diff > SLICE_RANGE;
    bool ispos = (diff <= SLICE_RANGE) && (j != i);

    // negatives: masked first half + all of the second half
    red[j] = (isneg ? e1 : 0.f) + e2;
    __syncthreads();
    for (int o = 128; o > 0; o >>= 1) {
        if (j < o) red[j] += red[j + o];
        __syncthreads();
    }
    float neg_sum = red[0];
    __syncthreads();

    // positive terms: -log(Sbb/(Sbb+neg)) = log(e1+neg) - s1/T
    red[j] = ispos ? (logf(e1 + neg_sum) - s1 * INV_TEMP) : 0.f;
    __syncthreads();
    for (int o = 128; o > 0; o >>= 1) {
        if (j < o) red[j] += red[j + o];
        __syncthreads();
    }
    float tsum = red[0];
    __syncthreads();

    red[j] = ispos ? 1.f : 0.f;
    __syncthreads();
    for (int o = 128; o > 0; o >>= 1) {
        if (j < o) red[j] += red[j + o];
        __syncthreads();
    }
    if (j == 0) {
        float cnt = red[0];
        g_lossb[i] = tsum / fmaxf(cnt, 1.f);
        g_cntd[i]  = (cnt > 0.f) ? 1.f : 0.f;
    }
}

// ---------------------------------------------------------------------------
// 8) deterministic final reduce -> out[0]=loss, out[1]=n_defined
// ---------------------------------------------------------------------------
__global__ void finalize_kernel(float* __restrict__ out, int out_size) {
    __shared__ float rl[256], rd[256];
    int t = threadIdx.x;
    rl[t] = g_lossb[t] * g_cntd[t];
    rd[t] = g_cntd[t];
    __syncthreads();
    for (int o = 128; o > 0; o >>= 1) {
        if (t < o) { rl[t] += rl[t + o]; rd[t] += rd[t + o]; }
        __syncthreads();
    }
    if (t == 0) {
        out[0] = rl[0];
        if (out_size > 1) out[1] = rd[0];
    }
}

// ---------------------------------------------------------------------------
extern "C" void kernel_launch(void* const* d_in, const int* in_sizes, int n_in,
                              void* d_out, int out_size) {
    const float* z0    = (const float*)d_in[0];
    const float* z1    = (const float*)d_in[1];
    const int*   rel0  = (const int*)d_in[2];
    // d_in[3] = rel_slice_idx_1: unused by the reference
    const float* W1    = (const float*)d_in[4];
    const float* b1    = (const float*)d_in[5];
    const float* gamma = (const float*)d_in[6];
    const float* beta  = (const float*)d_in[7];
    const float* W2    = (const float*)d_in[8];
    const float* b2    = (const float*)d_in[9];

    void *pb_, *w1b_, *w2b_, *h_, *hb_, *z_, *znb_, *sim_;
    cudaGetSymbolAddress(&pb_,  g_pb);
    cudaGetSymbolAddress(&w1b_, g_W1b);
    cudaGetSymbolAddress(&w2b_, g_W2b);
    cudaGetSymbolAddress(&h_,   g_h);
    cudaGetSymbolAddress(&hb_,  g_hb);
    cudaGetSymbolAddress(&z_,   g_z);
    cudaGetSymbolAddress(&znb_, g_znb);
    cudaGetSymbolAddress(&sim_, g_sim);

    // 1) pool: one warp per (b,d); 512*2048 warps, 8 warps/block
    pool_kernel<<<(TWOB * DIM) / 8, 256>>>(z0, z1);
    // 2) weight conversion (2 * 1M float4 groups)
    cvt_kernel<<<(2 * DIM * DIM / 4) / 256, 256>>>(W1, W2);
    // 3) GEMM1: h = p @ W1^T + b1
    gemm_kernel<<<dim3(DIM / BN, TWOB / BM), 256>>>(
        (const bf16*)pb_, (const bf16*)w1b_, (float*)h_, b1, TWOB, DIM, DIM);
    // 4) BN stats
    bn_stats_kernel<<<DIM / 32, 256>>>();
    // 5) BN apply + ReLU -> bf16
    bn_apply_kernel<<<(TWOB * DIM) / 256, 256>>>(gamma, beta);
    // 6) GEMM2: z = hb @ W2^T + b2
    gemm_kernel<<<dim3(DIM / BN, TWOB / BM), 256>>>(
        (const bf16*)hb_, (const bf16*)w2b_, (float*)z_, b2, TWOB, DIM, DIM);
    // 7) row normalize -> bf16
    rownorm_kernel<<<TWOB, 256>>>();
    // 8) sim = zn[:256] @ zn[:512]^T
    gemm_kernel<<<dim3(TWOB / BN, BATCH / BM), 256>>>(
        (const bf16*)znb_, (const bf16*)znb_, (float*)sim_, nullptr,
        BATCH, TWOB, DIM);
    // 9) per-row loss
    loss_rows_kernel<<<BATCH, 256>>>(rel0);
    // 10) deterministic finalize
    finalize_kernel<<<1, 256>>>((float*)d_out, out_size);
}

// round 2
// speedup vs baseline: 1.6159x; 1.6159x over previous
#include <cuda_runtime.h>
#include <cuda_bf16.h>
#include <math.h>

#define BATCH 256
#define TWOB 512
#define DIM 2048
#define HW 64
#define INV_TEMP 10.0f
#define BN_EPS 1e-5f
#define COS_EPS 1e-8f
#define SLICE_RANGE 2

typedef __nv_bfloat16 bf16;

// ---- scratch (device globals: no allocations allowed) ----
__device__ bf16  g_pb[TWOB * DIM];        // pooled, bf16
__device__ bf16  g_W1b[DIM * DIM];
__device__ bf16  g_W2b[DIM * DIM];
__device__ float g_h[TWOB * DIM];         // GEMM1 out (pre-BN)
__device__ float g_ps[8 * DIM];           // bn partial sums
__device__ float g_pq[8 * DIM];           // bn partial sumsq
__device__ float g_mu[DIM];
__device__ float g_istd[DIM];
__device__ bf16  g_hb[TWOB * DIM];        // BN+ReLU, bf16
__device__ float g_z[TWOB * DIM];         // GEMM2 out
__device__ bf16  g_znb[TWOB * DIM];       // normalized rows, bf16
__device__ float g_simp[4 * BATCH * TWOB];// split-K partial similarity
__device__ float g_lossb[BATCH];
__device__ float g_cntd[BATCH];

__device__ __forceinline__ unsigned smem_u32(const void* p) {
    return (unsigned)__cvta_generic_to_shared(p);
}

// ---------------------------------------------------------------------------
// 1) spatial mean pool: 2 channels per warp, float4 per lane (512B/warp)
// ---------------------------------------------------------------------------
__global__ void pool_kernel(const float* __restrict__ z0,
                            const float* __restrict__ z1) {
    int gt   = blockIdx.x * blockDim.x + threadIdx.x;
    int warp = gt >> 5;
    int lane = gt & 31;
    int ch   = warp * 2 + (lane >> 4);      // channel index 0 .. TWOB*DIM-1
    const float* src = (ch < BATCH * DIM)
                         ? z0 + (size_t)ch * HW
                         : z1 + (size_t)(ch - BATCH * DIM) * HW;
    float4 v = ((const float4*)src)[lane & 15];
    float s = (v.x + v.y) + (v.z + v.w);
#pragma unroll
    for (int o = 8; o > 0; o >>= 1) s += __shfl_xor_sync(0xffffffffu, s, o);
    if ((lane & 15) == 0) g_pb[ch] = __float2bfloat16(s * (1.0f / 64.0f));
}

// ---------------------------------------------------------------------------
// 2) weights f32 -> bf16
// ---------------------------------------------------------------------------
__global__ void cvt_kernel(const float* __restrict__ W1,
                           const float* __restrict__ W2) {
    const int NPER = DIM * DIM / 4;
    int i = blockIdx.x * blockDim.x + threadIdx.x;
    const float* src;
    bf16* dst;
    int j;
    if (i < NPER) { src = W1; dst = g_W1b; j = i; }
    else          { src = W2; dst = g_W2b; j = i - NPER; }
    float4 v = ((const float4*)src)[j];
    __nv_bfloat162 lo = __floats2bfloat162_rn(v.x, v.y);
    __nv_bfloat162 hi = __floats2bfloat162_rn(v.z, v.w);
    ((__nv_bfloat162*)dst)[j * 2]     = lo;
    ((__nv_bfloat162*)dst)[j * 2 + 1] = hi;
}

// ---------------------------------------------------------------------------
// 3) bf16 GEMM: C[M,N] = A[M,K] * B[N,K]^T (+bias), K-major operands.
//    cp.async double-buffered, BK=32, ldmatrix.x4 fragment loads.
//    Warp tile 32x32 (2 m16 x 4 n8). blockIdx.z = split-K chunk.
// ---------------------------------------------------------------------------
#define BK 32
#define SPAD 40   // bf16 per smem row (80B): conflict-free ldmatrix + 16B aligned

template<int BM, int BN, int WM, int WN, int TPB, int MAXB>
__global__ void __launch_bounds__(TPB, MAXB) gemm_kernel(
    const bf16* __restrict__ A, const bf16* __restrict__ Bm,
    float* __restrict__ C, const float* __restrict__ bias,
    int N, int K, int kChunk, int Mtot) {
    __shared__ bf16 As[2][BM * SPAD];
    __shared__ bf16 Bs[2][BN * SPAD];
    const int tid  = threadIdx.x;
    const int warp = tid >> 5;
    const int lane = tid & 31;
    const int wm = warp / WN;
    const int wn = warp % WN;
    const int rowBase = blockIdx.y * BM;
    const int colBase = blockIdx.x * BN;
    const int kOff    = blockIdx.z * kChunk;
    float* Cout = C + (size_t)blockIdx.z * Mtot * N;

    const bf16* Ag = A + (size_t)rowBase * K + kOff;
    const bf16* Bg = Bm + (size_t)colBase * K + kOff;

    auto loadStage = [&](int buf, int it) {
        int kb = it * BK;
#pragma unroll
        for (int c = tid; c < BM * 4; c += TPB) {
            int r = c >> 2, chk = c & 3;
            unsigned sa = smem_u32(&As[buf][r * SPAD + chk * 8]);
            asm volatile("cp.async.cg.shared.global [%0], [%1], 16;\n"
                         :: "r"(sa), "l"(Ag + (size_t)r * K + kb + chk * 8));
        }
#pragma unroll
        for (int c = tid; c < BN * 4; c += TPB) {
            int r = c >> 2, chk = c & 3;
            unsigned sa = smem_u32(&Bs[buf][r * SPAD + chk * 8]);
            asm volatile("cp.async.cg.shared.global [%0], [%1], 16;\n"
                         :: "r"(sa), "l"(Bg + (size_t)r * K + kb + chk * 8));
        }
        asm volatile("cp.async.commit_group;\n");
    };

    float acc[2][4][4];
#pragma unroll
    for (int i = 0; i < 2; i++)
#pragma unroll
        for (int j = 0; j < 4; j++)
#pragma unroll
            for (int k = 0; k < 4; k++) acc[i][j][k] = 0.f;

    const int NIT = kChunk / BK;
    loadStage(0, 0);

    const int arow = lane & 15;          // ldmatrix row index within 16
    const int acol = (lane >> 4) * 8;    // 0 or 8 (k half of an 8-col group)

    for (int it = 0; it < NIT; ++it) {
        asm volatile("cp.async.wait_group 0;\n" ::: "memory");
        __syncthreads();
        if (it + 1 < NIT) loadStage((it + 1) & 1, it + 1);
        const int buf = it & 1;

#pragma unroll
        for (int ks = 0; ks < 2; ++ks) {
            unsigned afr[2][4], bfr[2][4];
#pragma unroll
            for (int mt = 0; mt < 2; mt++) {
                unsigned sa = smem_u32(
                    &As[buf][(wm * 32 + mt * 16 + arow) * SPAD + acol + ks * 16]);
                asm volatile(
                    "ldmatrix.sync.aligned.m8n8.x4.shared.b16 {%0,%1,%2,%3}, [%4];\n"
                    : "=r"(afr[mt][0]), "=r"(afr[mt][1]),
                      "=r"(afr[mt][2]), "=r"(afr[mt][3]) : "r"(sa));
            }
#pragma unroll
            for (int np = 0; np < 2; np++) {
                unsigned sa = smem_u32(
                    &Bs[buf][(wn * 32 + np * 16 + arow) * SPAD + acol + ks * 16]);
                asm volatile(
                    "ldmatrix.sync.aligned.m8n8.x4.shared.b16 {%0,%1,%2,%3}, [%4];\n"
                    : "=r"(bfr[np][0]), "=r"(bfr[np][1]),
                      "=r"(bfr[np][2]), "=r"(bfr[np][3]) : "r"(sa));
            }
#pragma unroll
            for (int mt = 0; mt < 2; mt++)
#pragma unroll
                for (int nt = 0; nt < 4; nt++) {
                    asm volatile(
                        "mma.sync.aligned.m16n8k16.row.col.f32.bf16.bf16.f32 "
                        "{%0,%1,%2,%3}, {%4,%5,%6,%7}, {%8,%9}, {%0,%1,%2,%3};\n"
                        : "+f"(acc[mt][nt][0]), "+f"(acc[mt][nt][1]),
                          "+f"(acc[mt][nt][2]), "+f"(acc[mt][nt][3])
                        : "r"(afr[mt][0]), "r"(afr[mt][1]),
                          "r"(afr[mt][2]), "r"(afr[mt][3]),
                          "r"(bfr[nt >> 1][nt & 1]), "r"(bfr[nt >> 1][2 + (nt & 1)]));
                }
        }
        __syncthreads();
    }

    const int g  = lane >> 2;
    const int t4 = lane & 3;
#pragma unroll
    for (int mt = 0; mt < 2; mt++) {
        int r0 = rowBase + wm * 32 + mt * 16 + g;
#pragma unroll
        for (int nt = 0; nt < 4; nt++) {
            int c0 = colBase + wn * 32 + nt * 8 + t4 * 2;
            float bx = bias ? bias[c0] : 0.f;
            float by = bias ? bias[c0 + 1] : 0.f;
            *(float2*)&Cout[(size_t)r0 * N + c0] =
                make_float2(acc[mt][nt][0] + bx, acc[mt][nt][1] + by);
            *(float2*)&Cout[(size_t)(r0 + 8) * N + c0] =
                make_float2(acc[mt][nt][2] + bx, acc[mt][nt][3] + by);
        }
    }
}

// ---------------------------------------------------------------------------
// 4a) BN partial stats: grid (8, 8); block x covers 256 cols, y covers 64 rows
// ---------------------------------------------------------------------------
__global__ void bn_partial_kernel() {
    int col = blockIdx.x * 256 + threadIdx.x;
    int r0  = blockIdx.y * 64;
    float s = 0.f, q = 0.f;
#pragma unroll 8
    for (int r = 0; r < 64; r++) {
        float v = g_h[(size_t)(r0 + r) * DIM + col];
        s += v; q += v * v;
    }
    g_ps[blockIdx.y * DIM + col] = s;
    g_pq[blockIdx.y * DIM + col] = q;
}

// 4b) BN finalize: reduce 8 partials per column
__global__ void bn_finalize_kernel() {
    int col = blockIdx.x * 256 + threadIdx.x;
    float s = 0.f, q = 0.f;
#pragma unroll
    for (int p = 0; p < 8; p++) { s += g_ps[p * DIM + col]; q += g_pq[p * DIM + col]; }
    float mu  = s * (1.f / TWOB);
    float var = q * (1.f / TWOB) - mu * mu;
    g_mu[col]   = mu;
    g_istd[col] = rsqrtf(var + BN_EPS);
}

// ---------------------------------------------------------------------------
// 5) BN apply + ReLU -> bf16
// ---------------------------------------------------------------------------
__global__ void bn_apply_kernel(const float* __restrict__ gamma,
                                const float* __restrict__ beta) {
    int i = blockIdx.x * blockDim.x + threadIdx.x;
    int d = i & (DIM - 1);
    float v = (g_h[i] - g_mu[d]) * g_istd[d] * gamma[d] + beta[d];
    g_hb[i] = __float2bfloat16(fmaxf(v, 0.f));
}

// ---------------------------------------------------------------------------
// 6) row L2 normalize -> bf16
// ---------------------------------------------------------------------------
__global__ void rownorm_kernel() {
    __shared__ float red[256];
    int r = blockIdx.x, tid = threadIdx.x;
    const float* row = g_z + (size_t)r * DIM;
    float s = 0.f;
    for (int d = tid; d < DIM; d += 256) { float v = row[d]; s += v * v; }
    red[tid] = s;
    __syncthreads();
    for (int o = 128; o > 0; o >>= 1) {
        if (tid < o) red[tid] += red[tid + o];
        __syncthreads();
    }
    float inv = 1.f / fmaxf(sqrtf(red[0]), COS_EPS);
    for (int d = tid; d < DIM; d += 256)
        g_znb[(size_t)r * DIM + d] = __float2bfloat16(row[d] * inv);
}

// ---------------------------------------------------------------------------
// 7) per-row contrastive loss; block i handles sim row i (sums 4 K-partials)
// ---------------------------------------------------------------------------
__global__ void loss_rows_kernel(const int* __restrict__ rel) {
    __shared__ float red[256];
    int i = blockIdx.x, j = threadIdx.x;
    int ri = rel[i];
    int rj = rel[j];
    float s1 = 0.f, s2 = 0.f;
#pragma unroll
    for (int p = 0; p < 4; p++) {
        s1 += g_simp[p * BATCH * TWOB + i * TWOB + j];
        s2 += g_simp[p * BATCH * TWOB + i * TWOB + BATCH + j];
    }
    float e1 = expf(s1 * INV_TEMP);
    float e2 = expf(s2 * INV_TEMP);
    int diff = ri - rj; if (diff < 0) diff = -diff;
    bool isneg = diff > SLICE_RANGE;
    bool ispos = (diff <= SLICE_RANGE) && (j != i);

    red[j] = (isneg ? e1 : 0.f) + e2;
    __syncthreads();
    for (int o = 128; o > 0; o >>= 1) {
        if (j < o) red[j] += red[j + o];
        __syncthreads();
    }
    float neg_sum = red[0];
    __syncthreads();

    red[j] = ispos ? (logf(e1 + neg_sum) - s1 * INV_TEMP) : 0.f;
    __syncthreads();
    for (int o = 128; o > 0; o >>= 1) {
        if (j < o) red[j] += red[j + o];
        __syncthreads();
    }
    float tsum = red[0];
    __syncthreads();

    red[j] = ispos ? 1.f : 0.f;
    __syncthreads();
    for (int o = 128; o > 0; o >>= 1) {
        if (j < o) red[j] += red[j + o];
        __syncthreads();
    }
    if (j == 0) {
        float cnt = red[0];
        g_lossb[i] = tsum / fmaxf(cnt, 1.f);
        g_cntd[i]  = (cnt > 0.f) ? 1.f : 0.f;
    }
}

// ---------------------------------------------------------------------------
// 8) deterministic final reduce -> out[0]=loss, out[1]=n_defined
// ---------------------------------------------------------------------------
__global__ void finalize_kernel(float* __restrict__ out, int out_size) {
    __shared__ float rl[256], rd[256];
    int t = threadIdx.x;
    rl[t] = g_lossb[t] * g_cntd[t];
    rd[t] = g_cntd[t];
    __syncthreads();
    for (int o = 128; o > 0; o >>= 1) {
        if (t < o) { rl[t] += rl[t + o]; rd[t] += rd[t + o]; }
        __syncthreads();
    }
    if (t == 0) {
        out[0] = rl[0];
        if (out_size > 1) out[1] = rd[0];
    }
}

// ---------------------------------------------------------------------------
extern "C" void kernel_launch(void* const* d_in, const int* in_sizes, int n_in,
                              void* d_out, int out_size) {
    const float* z0    = (const float*)d_in[0];
    const float* z1    = (const float*)d_in[1];
    const int*   rel0  = (const int*)d_in[2];
    const float* W1    = (const float*)d_in[4];
    const float* b1    = (const float*)d_in[5];
    const float* gamma = (const float*)d_in[6];
    const float* beta  = (const float*)d_in[7];
    const float* W2    = (const float*)d_in[8];
    const float* b2    = (const float*)d_in[9];

    void *pb_, *w1b_, *w2b_, *h_, *hb_, *z_, *znb_, *simp_;
    cudaGetSymbolAddress(&pb_,  g_pb);
    cudaGetSymbolAddress(&w1b_, g_W1b);
    cudaGetSymbolAddress(&w2b_, g_W2b);
    cudaGetSymbolAddress(&h_,   g_h);
    cudaGetSymbolAddress(&hb_,  g_hb);
    cudaGetSymbolAddress(&z_,   g_z);
    cudaGetSymbolAddress(&znb_, g_znb);
    cudaGetSymbolAddress(&simp_, g_simp);

    // 1) pool: 2 channels per warp
    pool_kernel<<<(TWOB * DIM / 2) / 8, 256>>>(z0, z1);
    // 2) weight conversion
    cvt_kernel<<<(2 * DIM * DIM / 4) / 256, 256>>>(W1, W2);
    // 3) GEMM1: h = p @ W1^T + b1  (128 blocks)
    gemm_kernel<128, 64, 4, 2, 256, 1><<<dim3(DIM / 64, TWOB / 128, 1), 256>>>(
        (const bf16*)pb_, (const bf16*)w1b_, (float*)h_, b1,
        DIM, DIM, DIM, TWOB);
    // 4) BN stats (two-stage)
    bn_partial_kernel<<<dim3(8, 8), 256>>>();
    bn_finalize_kernel<<<8, 256>>>();
    // 5) BN apply + ReLU -> bf16
    bn_apply_kernel<<<(TWOB * DIM) / 256, 256>>>(gamma, beta);
    // 6) GEMM2: z = hb @ W2^T + b2
    gemm_kernel<128, 64, 4, 2, 256, 1><<<dim3(DIM / 64, TWOB / 128, 1), 256>>>(
        (const bf16*)hb_, (const bf16*)w2b_, (float*)z_, b2,
        DIM, DIM, DIM, TWOB);
    // 7) row normalize -> bf16
    rownorm_kernel<<<TWOB, 256>>>();
    // 8) sim partials: 64x64 tiles, split-K=4 -> 128 blocks
    gemm_kernel<64, 64, 2, 2, 128, 1><<<dim3(TWOB / 64, BATCH / 64, 4), 128>>>(
        (const bf16*)znb_, (const bf16*)znb_, (float*)simp_, nullptr,
        TWOB, DIM, DIM / 4, BATCH);
    // 9) per-row loss
    loss_rows_kernel<<<BATCH, 256>>>(rel0);
    // 10) deterministic finalize
    finalize_kernel<<<1, 256>>>((float*)d_out, out_size);
}

// round 3
// speedup vs baseline: 1.7808x; 1.1020x over previous
#include <cuda_runtime.h>
#include <cuda_bf16.h>
#include <math.h>

#define BATCH 256
#define TWOB 512
#define DIM 2048
#define HW 64
#define INV_TEMP 10.0f
#define BN_EPS 1e-5f
#define COS_EPS 1e-8f
#define SLICE_RANGE 2

typedef __nv_bfloat16 bf16;

// ---- scratch (device globals: no allocations allowed) ----
__device__ bf16  g_pb[TWOB * DIM];        // pooled, bf16
__device__ bf16  g_W1b[DIM * DIM];
__device__ bf16  g_W2b[DIM * DIM];
__device__ float g_h[TWOB * DIM];         // GEMM1 out (pre-BN)
__device__ float g_ps[8 * DIM];           // bn partial sums (per row-block)
__device__ float g_pq[8 * DIM];           // bn partial sumsq
__device__ bf16  g_hb[TWOB * DIM];        // BN+ReLU, bf16
__device__ float g_z[TWOB * DIM];         // GEMM2 out
__device__ bf16  g_znb[TWOB * DIM];       // normalized rows, bf16
__device__ float g_simp[4 * BATCH * TWOB];// split-K partial similarity
__device__ float g_lossb[BATCH];
__device__ float g_cntd[BATCH];

__device__ __forceinline__ unsigned smem_u32(const void* p) {
    return (unsigned)__cvta_generic_to_shared(p);
}

// ---------------------------------------------------------------------------
// 1) prep: spatial mean pool (block range A) + weight f32->bf16 (block range B)
// ---------------------------------------------------------------------------
#define POOL_BLOCKS ((TWOB * DIM / 2) / 8)          // 65536
#define CVT_BLOCKS  ((2 * DIM * DIM / 4) / 256)     // 8192

__global__ void prep_kernel(const float* __restrict__ z0,
                            const float* __restrict__ z1,
                            const float* __restrict__ W1,
                            const float* __restrict__ W2) {
    if (blockIdx.x < POOL_BLOCKS) {
        int gt   = blockIdx.x * 256 + threadIdx.x;
        int warp = gt >> 5;
        int lane = gt & 31;
        int ch   = warp * 2 + (lane >> 4);
        const float* src = (ch < BATCH * DIM)
                             ? z0 + (size_t)ch * HW
                             : z1 + (size_t)(ch - BATCH * DIM) * HW;
        float4 v = ((const float4*)src)[lane & 15];
        float s = (v.x + v.y) + (v.z + v.w);
#pragma unroll
        for (int o = 8; o > 0; o >>= 1)
            s += __shfl_xor_sync(0xffffffffu, s, o);
        if ((lane & 15) == 0) g_pb[ch] = __float2bfloat16(s * (1.0f / 64.0f));
    } else {
        const int NPER = DIM * DIM / 4;
        int i = (blockIdx.x - POOL_BLOCKS) * 256 + threadIdx.x;
        const float* src;
        bf16* dst;
        int j;
        if (i < NPER) { src = W1; dst = g_W1b; j = i; }
        else          { src = W2; dst = g_W2b; j = i - NPER; }
        float4 v = ((const float4*)src)[j];
        __nv_bfloat162 lo = __floats2bfloat162_rn(v.x, v.y);
        __nv_bfloat162 hi = __floats2bfloat162_rn(v.z, v.w);
        ((__nv_bfloat162*)dst)[j * 2]     = lo;
        ((__nv_bfloat162*)dst)[j * 2 + 1] = hi;
    }
}

// ---------------------------------------------------------------------------
// 2) bf16 GEMM: C[M,N] = A[M,K]*B[N,K]^T (+bias). 64x64 tile, 4 warps (2x2),
//    warp tile 32x32. 3-stage cp.async pipeline, ldmatrix.x4 fragments.
//    STATS: per-block BN column stats written to g_ps/g_pq (GEMM1 only).
//    blockIdx.z = split-K chunk (sim GEMM).
// ---------------------------------------------------------------------------
#define BK 32
#define SPAD 40   // bf16 per smem row (80B): conflict-free ldmatrix

template<bool STATS>
__global__ void __launch_bounds__(128, 3) gemm_kernel(
    const bf16* __restrict__ A, const bf16* __restrict__ Bm,
    float* __restrict__ C, const float* __restrict__ bias,
    int N, int K, int kChunk, int Mtot) {
    constexpr int BM = 64, BN = 64, TPB = 128;
    __shared__ bf16 As[3][BM * SPAD];
    __shared__ bf16 Bs[3][BN * SPAD];
    __shared__ float sS[2][64], sQ[2][64];

    const int tid  = threadIdx.x;
    const int warp = tid >> 5;
    const int lane = tid & 31;
    const int wm = warp >> 1;
    const int wn = warp & 1;
    const int rowBase = blockIdx.y * BM;
    const int colBase = blockIdx.x * BN;
    const int kOff    = blockIdx.z * kChunk;
    float* Cout = C + (size_t)blockIdx.z * Mtot * N;

    const bf16* Ag = A + (size_t)rowBase * K + kOff;
    const bf16* Bg = Bm + (size_t)colBase * K + kOff;

    auto loadStage = [&](int st, int it) {
        int kb = it * BK;
#pragma unroll
        for (int c = tid; c < BM * 4; c += TPB) {
            int r = c >> 2, chk = c & 3;
            unsigned sa = smem_u32(&As[st][r * SPAD + chk * 8]);
            asm volatile("cp.async.cg.shared.global [%0], [%1], 16;\n"
                         :: "r"(sa), "l"(Ag + (size_t)r * K + kb + chk * 8));
        }
#pragma unroll
        for (int c = tid; c < BN * 4; c += TPB) {
            int r = c >> 2, chk = c & 3;
            unsigned sa = smem_u32(&Bs[st][r * SPAD + chk * 8]);
            asm volatile("cp.async.cg.shared.global [%0], [%1], 16;\n"
                         :: "r"(sa), "l"(Bg + (size_t)r * K + kb + chk * 8));
        }
        asm volatile("cp.async.commit_group;\n");
    };

    float acc[2][4][4];
#pragma unroll
    for (int i = 0; i < 2; i++)
#pragma unroll
        for (int j = 0; j < 4; j++)
#pragma unroll
            for (int k = 0; k < 4; k++) acc[i][j][k] = 0.f;

    const int NIT = kChunk / BK;
    loadStage(0, 0);
    loadStage(1, 1);

    const int arow = lane & 15;
    const int acol = (lane >> 4) * 8;

    for (int it = 0; it < NIT; ++it) {
        asm volatile("cp.async.wait_group 1;\n" ::: "memory");
        __syncthreads();
        if (it + 2 < NIT) loadStage((it + 2) % 3, it + 2);
        else asm volatile("cp.async.commit_group;\n");
        const int buf = it % 3;

#pragma unroll
        for (int ks = 0; ks < 2; ++ks) {
            unsigned afr[2][4], bfr[2][4];
#pragma unroll
            for (int mt = 0; mt < 2; mt++) {
                unsigned sa = smem_u32(
                    &As[buf][(wm * 32 + mt * 16 + arow) * SPAD + acol + ks * 16]);
                asm volatile(
                    "ldmatrix.sync.aligned.m8n8.x4.shared.b16 {%0,%1,%2,%3}, [%4];\n"
                    : "=r"(afr[mt][0]), "=r"(afr[mt][1]),
                      "=r"(afr[mt][2]), "=r"(afr[mt][3]) : "r"(sa));
            }
#pragma unroll
            for (int np = 0; np < 2; np++) {
                unsigned sa = smem_u32(
                    &Bs[buf][(wn * 32 + np * 16 + arow) * SPAD + acol + ks * 16]);
                asm volatile(
                    "ldmatrix.sync.aligned.m8n8.x4.shared.b16 {%0,%1,%2,%3}, [%4];\n"
                    : "=r"(bfr[np][0]), "=r"(bfr[np][1]),
                      "=r"(bfr[np][2]), "=r"(bfr[np][3]) : "r"(sa));
            }
#pragma unroll
            for (int mt = 0; mt < 2; mt++)
#pragma unroll
                for (int nt = 0; nt < 4; nt++) {
                    asm volatile(
                        "mma.sync.aligned.m16n8k16.row.col.f32.bf16.bf16.f32 "
                        "{%0,%1,%2,%3}, {%4,%5,%6,%7}, {%8,%9}, {%0,%1,%2,%3};\n"
                        : "+f"(acc[mt][nt][0]), "+f"(acc[mt][nt][1]),
                          "+f"(acc[mt][nt][2]), "+f"(acc[mt][nt][3])
                        : "r"(afr[mt][0]), "r"(afr[mt][1]),
                          "r"(afr[mt][2]), "r"(afr[mt][3]),
                          "r"(bfr[nt >> 1][nt & 1]), "r"(bfr[nt >> 1][2 + (nt & 1)]));
                }
        }
        __syncthreads();
    }

    const int g  = lane >> 2;
    const int t4 = lane & 3;

    // bias folded into accumulators first (stats must include it)
#pragma unroll
    for (int mt = 0; mt < 2; mt++)
#pragma unroll
        for (int nt = 0; nt < 4; nt++) {
            int c0 = colBase + wn * 32 + nt * 8 + t4 * 2;
            float bx = bias ? bias[c0] : 0.f;
            float by = bias ? bias[c0 + 1] : 0.f;
            acc[mt][nt][0] += bx; acc[mt][nt][1] += by;
            acc[mt][nt][2] += bx; acc[mt][nt][3] += by;
        }

#pragma unroll
    for (int mt = 0; mt < 2; mt++) {
        int r0 = rowBase + wm * 32 + mt * 16 + g;
#pragma unroll
        for (int nt = 0; nt < 4; nt++) {
            int c0 = colBase + wn * 32 + nt * 8 + t4 * 2;
            *(float2*)&Cout[(size_t)r0 * N + c0] =
                make_float2(acc[mt][nt][0], acc[mt][nt][1]);
            *(float2*)&Cout[(size_t)(r0 + 8) * N + c0] =
                make_float2(acc[mt][nt][2], acc[mt][nt][3]);
        }
    }

    if (STATS) {
#pragma unroll
        for (int nt = 0; nt < 4; nt++) {
            float s0 = 0.f, s1 = 0.f, q0 = 0.f, q1 = 0.f;
#pragma unroll
            for (int mt = 0; mt < 2; mt++) {
                float v0 = acc[mt][nt][0], v1 = acc[mt][nt][1];
                float v2 = acc[mt][nt][2], v3 = acc[mt][nt][3];
                s0 += v0 + v2; q0 += v0 * v0 + v2 * v2;
                s1 += v1 + v3; q1 += v1 * v1 + v3 * v3;
            }
#pragma unroll
            for (int o = 4; o <= 16; o <<= 1) {
                s0 += __shfl_xor_sync(0xffffffffu, s0, o);
                s1 += __shfl_xor_sync(0xffffffffu, s1, o);
                q0 += __shfl_xor_sync(0xffffffffu, q0, o);
                q1 += __shfl_xor_sync(0xffffffffu, q1, o);
            }
            if (lane < 4) {
                int ci = wn * 32 + nt * 8 + lane * 2;
                sS[wm][ci] = s0; sS[wm][ci + 1] = s1;
                sQ[wm][ci] = q0; sQ[wm][ci + 1] = q1;
            }
        }
        __syncthreads();
        if (tid < 64) {
            g_ps[blockIdx.y * DIM + colBase + tid] = sS[0][tid] + sS[1][tid];
            g_pq[blockIdx.y * DIM + colBase + tid] = sQ[0][tid] + sQ[1][tid];
        }
    }
}

// ---------------------------------------------------------------------------
// 3) BN finalize + apply + ReLU -> bf16. grid (8,8): 256 cols x 64 rows/block
// ---------------------------------------------------------------------------
__global__ void bn_apply_kernel(const float* __restrict__ gamma,
                                const float* __restrict__ beta) {
    int col = blockIdx.x * 256 + threadIdx.x;
    float s = 0.f, q = 0.f;
#pragma unroll
    for (int p = 0; p < 8; p++) {
        s += g_ps[p * DIM + col];
        q += g_pq[p * DIM + col];
    }
    float mu   = s * (1.f / TWOB);
    float var  = q * (1.f / TWOB) - mu * mu;
    float istd = rsqrtf(var + BN_EPS);
    float ga = gamma[col] * istd;
    float be = beta[col] - mu * ga;
    int r0 = blockIdx.y * 64;
#pragma unroll 4
    for (int r = 0; r < 64; r++) {
        size_t i = (size_t)(r0 + r) * DIM + col;
        g_hb[i] = __float2bfloat16(fmaxf(g_h[i] * ga + be, 0.f));
    }
}

// ---------------------------------------------------------------------------
// 4) row L2 normalize -> bf16 (float4 IO)
// ---------------------------------------------------------------------------
__global__ void rownorm_kernel() {
    __shared__ float red[256];
    int r = blockIdx.x, tid = threadIdx.x;
    const float4* row4 = (const float4*)(g_z + (size_t)r * DIM);
    float4 a = row4[tid];
    float4 b = row4[tid + 256];
    float s = a.x * a.x + a.y * a.y + a.z * a.z + a.w * a.w
            + b.x * b.x + b.y * b.y + b.z * b.z + b.w * b.w;
    red[tid] = s;
    __syncthreads();
    for (int o = 128; o > 0; o >>= 1) {
        if (tid < o) red[tid] += red[tid + o];
        __syncthreads();
    }
    float inv = 1.f / fmaxf(sqrtf(red[0]), COS_EPS);
    __nv_bfloat162* dst = (__nv_bfloat162*)(g_znb + (size_t)r * DIM);
    dst[tid * 2]       = __floats2bfloat162_rn(a.x * inv, a.y * inv);
    dst[tid * 2 + 1]   = __floats2bfloat162_rn(a.z * inv, a.w * inv);
    dst[(tid + 256) * 2]     = __floats2bfloat162_rn(b.x * inv, b.y * inv);
    dst[(tid + 256) * 2 + 1] = __floats2bfloat162_rn(b.z * inv, b.w * inv);
}

// ---------------------------------------------------------------------------
// 5) per-row contrastive loss; block i handles sim row i (sums 4 K-partials)
// ---------------------------------------------------------------------------
__global__ void loss_rows_kernel(const int* __restrict__ rel) {
    __shared__ float red[256];
    int i = blockIdx.x, j = threadIdx.x;
    int ri = rel[i];
    int rj = rel[j];
    float s1 = 0.f, s2 = 0.f;
#pragma unroll
    for (int p = 0; p < 4; p++) {
        s1 += g_simp[p * BATCH * TWOB + i * TWOB + j];
        s2 += g_simp[p * BATCH * TWOB + i * TWOB + BATCH + j];
    }
    float e1 = expf(s1 * INV_TEMP);
    float e2 = expf(s2 * INV_TEMP);
    int diff = ri - rj; if (diff < 0) diff = -diff;
    bool isneg = diff > SLICE_RANGE;
    bool ispos = (diff <= SLICE_RANGE) && (j != i);

    red[j] = (isneg ? e1 : 0.f) + e2;
    __syncthreads();
    for (int o = 128; o > 0; o >>= 1) {
        if (j < o) red[j] += red[j + o];
        __syncthreads();
    }
    float neg_sum = red[0];
    __syncthreads();

    red[j] = ispos ? (logf(e1 + neg_sum) - s1 * INV_TEMP) : 0.f;
    __syncthreads();
    for (int o = 128; o > 0; o >>= 1) {
        if (j < o) red[j] += red[j + o];
        __syncthreads();
    }
    float tsum = red[0];
    __syncthreads();

    red[j] = ispos ? 1.f : 0.f;
    __syncthreads();
    for (int o = 128; o > 0; o >>= 1) {
        if (j < o) red[j] += red[j + o];
        __syncthreads();
    }
    if (j == 0) {
        float cnt = red[0];
        g_lossb[i] = tsum / fmaxf(cnt, 1.f);
        g_cntd[i]  = (cnt > 0.f) ? 1.f : 0.f;
    }
}

// ---------------------------------------------------------------------------
// 6) deterministic final reduce -> out[0]=loss, out[1]=n_defined
// ---------------------------------------------------------------------------
__global__ void finalize_kernel(float* __restrict__ out, int out_size) {
    __shared__ float rl[256], rd[256];
    int t = threadIdx.x;
    rl[t] = g_lossb[t] * g_cntd[t];
    rd[t] = g_cntd[t];
    __syncthreads();
    for (int o = 128; o > 0; o >>= 1) {
        if (t < o) { rl[t] += rl[t + o]; rd[t] += rd[t + o]; }
        __syncthreads();
    }
    if (t == 0) {
        out[0] = rl[0];
        if (out_size > 1) out[1] = rd[0];
    }
}

// ---------------------------------------------------------------------------
extern "C" void kernel_launch(void* const* d_in, const int* in_sizes, int n_in,
                              void* d_out, int out_size) {
    const float* z0    = (const float*)d_in[0];
    const float* z1    = (const float*)d_in[1];
    const int*   rel0  = (const int*)d_in[2];
    const float* W1    = (const float*)d_in[4];
    const float* b1    = (const float*)d_in[5];
    const float* gamma = (const float*)d_in[6];
    const float* beta  = (const float*)d_in[7];
    const float* W2    = (const float*)d_in[8];
    const float* b2    = (const float*)d_in[9];

    void *pb_, *w1b_, *w2b_, *h_, *hb_, *z_, *znb_, *simp_;
    cudaGetSymbolAddress(&pb_,  g_pb);
    cudaGetSymbolAddress(&w1b_, g_W1b);
    cudaGetSymbolAddress(&w2b_, g_W2b);
    cudaGetSymbolAddress(&h_,   g_h);
    cudaGetSymbolAddress(&hb_,  g_hb);
    cudaGetSymbolAddress(&z_,   g_z);
    cudaGetSymbolAddress(&znb_, g_znb);
    cudaGetSymbolAddress(&simp_, g_simp);

    // 1) pool + weight conversion
    prep_kernel<<<POOL_BLOCKS + CVT_BLOCKS, 256>>>(z0, z1, W1, W2);
    // 2) GEMM1: h = p @ W1^T + b1, with fused BN partial stats (256 blocks)
    gemm_kernel<true><<<dim3(DIM / 64, TWOB / 64, 1), 128>>>(
        (const bf16*)pb_, (const bf16*)w1b_, (float*)h_, b1,
        DIM, DIM, DIM, TWOB);
    // 3) BN finalize + apply + ReLU -> bf16
    bn_apply_kernel<<<dim3(8, 8), 256>>>(gamma, beta);
    // 4) GEMM2: z = hb @ W2^T + b2
    gemm_kernel<false><<<dim3(DIM / 64, TWOB / 64, 1), 128>>>(
        (const bf16*)hb_, (const bf16*)w2b_, (float*)z_, b2,
        DIM, DIM, DIM, TWOB);
    // 5) row normalize -> bf16
    rownorm_kernel<<<TWOB, 256>>>();
    // 6) sim partials: 64x64 tiles, split-K=4 -> 128 blocks
    gemm_kernel<false><<<dim3(TWOB / 64, BATCH / 64, 4), 128>>>(
        (const bf16*)znb_, (const bf16*)znb_, (float*)simp_, nullptr,
        TWOB, DIM, DIM / 4, BATCH);
    // 7) per-row loss
    loss_rows_kernel<<<BATCH, 256>>>(rel0);
    // 8) deterministic finalize
    finalize_kernel<<<1, 256>>>((float*)d_out, out_size);
}

// round 5
// speedup vs baseline: 1.9023x; 1.0683x over previous
#include <cuda_runtime.h>
#include <cuda_bf16.h>
#include <math.h>

#define BATCH 256
#define TWOB 512
#define DIM 2048
#define HW 64
#define INV_TEMP 10.0f
#define BN_EPS 1e-5f
#define COS_EPS 1e-8f
#define SLICE_RANGE 2

typedef __nv_bfloat16 bf16;

// ---- scratch (device globals: no allocations allowed) ----
__device__ bf16  g_pb[TWOB * DIM];         // pooled, bf16
__device__ bf16  g_W1b[DIM * DIM];
__device__ bf16  g_W2b[DIM * DIM];
__device__ float g_hp[2 * TWOB * DIM];     // GEMM1 split-K partials
__device__ float g_ps[32 * DIM];           // bn partial sums
__device__ float g_pq[32 * DIM];           // bn partial sumsq
__device__ bf16  g_hb[TWOB * DIM];         // BN+ReLU, bf16
__device__ float g_zp[2 * TWOB * DIM];     // GEMM2 split-K partials
__device__ bf16  g_znb[TWOB * DIM];        // normalized rows, bf16
__device__ float g_simp[4 * BATCH * TWOB]; // sim split-K partials
__device__ float g_lossb[BATCH];
__device__ float g_cntd[BATCH];

__device__ __forceinline__ unsigned smem_u32(const void* p) {
    return (unsigned)__cvta_generic_to_shared(p);
}

// ---------------------------------------------------------------------------
// 1) prep: spatial mean pool (block range A) + weight f32->bf16 (block range B)
// ---------------------------------------------------------------------------
#define POOL_BLOCKS ((TWOB * DIM / 2) / 8)          // 65536
#define CVT_BLOCKS  ((2 * DIM * DIM / 4) / 256)     // 8192

__global__ void prep_kernel(const float* __restrict__ z0,
                            const float* __restrict__ z1,
                            const float* __restrict__ W1,
                            const float* __restrict__ W2) {
    if (blockIdx.x < POOL_BLOCKS) {
        int gt   = blockIdx.x * 256 + threadIdx.x;
        int warp = gt >> 5;
        int lane = gt & 31;
        int ch   = warp * 2 + (lane >> 4);
        const float* src = (ch < BATCH * DIM)
                             ? z0 + (size_t)ch * HW
                             : z1 + (size_t)(ch - BATCH * DIM) * HW;
        float4 v = ((const float4*)src)[lane & 15];
        float s = (v.x + v.y) + (v.z + v.w);
#pragma unroll
        for (int o = 8; o > 0; o >>= 1)
            s += __shfl_xor_sync(0xffffffffu, s, o);
        if ((lane & 15) == 0) g_pb[ch] = __float2bfloat16(s * (1.0f / 64.0f));
    } else {
        const int NPER = DIM * DIM / 4;
        int i = (blockIdx.x - POOL_BLOCKS) * 256 + threadIdx.x;
        const float* src;
        bf16* dst;
        int j;
        if (i < NPER) { src = W1; dst = g_W1b; j = i; }
        else          { src = W2; dst = g_W2b; j = i - NPER; }
        float4 v = ((const float4*)src)[j];
        ((__nv_bfloat162*)dst)[j * 2]     = __floats2bfloat162_rn(v.x, v.y);
        ((__nv_bfloat162*)dst)[j * 2 + 1] = __floats2bfloat162_rn(v.z, v.w);
    }
}

// ---------------------------------------------------------------------------
// 2) bf16 GEMM: C[M,N] = A[M,K]*B[N,K]^T (+bias). 64x64 tile, 4 warps (2x2),
//    warp tile 32x32. 3-stage cp.async pipeline, ldmatrix.x4 fragments.
//    blockIdx.z = split-K chunk, writes into partial buffer z*Mtot*N.
// ---------------------------------------------------------------------------
#define BK 32
#define SPAD 40   // bf16 per smem row (80B): conflict-free ldmatrix

__global__ void __launch_bounds__(128, 3) gemm_kernel(
    const bf16* __restrict__ A, const bf16* __restrict__ Bm,
    float* __restrict__ C, const float* __restrict__ bias,
    int N, int K, int kChunk, int Mtot) {
    constexpr int BM = 64, BN = 64, TPB = 128;
    __shared__ bf16 As[3][BM * SPAD];
    __shared__ bf16 Bs[3][BN * SPAD];

    const int tid  = threadIdx.x;
    const int warp = tid >> 5;
    const int lane = tid & 31;
    const int wm = warp >> 1;
    const int wn = warp & 1;
    const int rowBase = blockIdx.y * BM;
    const int colBase = blockIdx.x * BN;
    const int kOff    = blockIdx.z * kChunk;
    float* Cout = C + (size_t)blockIdx.z * Mtot * N;

    const bf16* Ag = A + (size_t)rowBase * K + kOff;
    const bf16* Bg = Bm + (size_t)colBase * K + kOff;

    auto loadStage = [&](int st, int it) {
        int kb = it * BK;
#pragma unroll
        for (int c = tid; c < BM * 4; c += TPB) {
            int r = c >> 2, chk = c & 3;
            unsigned sa = smem_u32(&As[st][r * SPAD + chk * 8]);
            asm volatile("cp.async.cg.shared.global [%0], [%1], 16;\n"
                         :: "r"(sa), "l"(Ag + (size_t)r * K + kb + chk * 8));
        }
#pragma unroll
        for (int c = tid; c < BN * 4; c += TPB) {
            int r = c >> 2, chk = c & 3;
            unsigned sa = smem_u32(&Bs[st][r * SPAD + chk * 8]);
            asm volatile("cp.async.cg.shared.global [%0], [%1], 16;\n"
                         :: "r"(sa), "l"(Bg + (size_t)r * K + kb + chk * 8));
        }
        asm volatile("cp.async.commit_group;\n");
    };

    float acc[2][4][4];
#pragma unroll
    for (int i = 0; i < 2; i++)
#pragma unroll
        for (int j = 0; j < 4; j++)
#pragma unroll
            for (int k = 0; k < 4; k++) acc[i][j][k] = 0.f;

    const int NIT = kChunk / BK;
    loadStage(0, 0);
    loadStage(1, 1);

    const int arow = lane & 15;
    const int acol = (lane >> 4) * 8;

    for (int it = 0; it < NIT; ++it) {
        asm volatile("cp.async.wait_group 1;\n" ::: "memory");
        __syncthreads();
        if (it + 2 < NIT) loadStage((it + 2) % 3, it + 2);
        else asm volatile("cp.async.commit_group;\n");
        const int buf = it % 3;

#pragma unroll
        for (int ks = 0; ks < 2; ++ks) {
            unsigned afr[2][4], bfr[2][4];
#pragma unroll
            for (int mt = 0; mt < 2; mt++) {
                unsigned sa = smem_u32(
                    &As[buf][(wm * 32 + mt * 16 + arow) * SPAD + acol + ks * 16]);
                asm volatile(
                    "ldmatrix.sync.aligned.m8n8.x4.shared.b16 {%0,%1,%2,%3}, [%4];\n"
                    : "=r"(afr[mt][0]), "=r"(afr[mt][1]),
                      "=r"(afr[mt][2]), "=r"(afr[mt][3]) : "r"(sa));
            }
#pragma unroll
            for (int np = 0; np < 2; np++) {
                unsigned sa = smem_u32(
                    &Bs[buf][(wn * 32 + np * 16 + arow) * SPAD + acol + ks * 16]);
                asm volatile(
                    "ldmatrix.sync.aligned.m8n8.x4.shared.b16 {%0,%1,%2,%3}, [%4];\n"
                    : "=r"(bfr[np][0]), "=r"(bfr[np][1]),
                      "=r"(bfr[np][2]), "=r"(bfr[np][3]) : "r"(sa));
            }
#pragma unroll
            for (int mt = 0; mt < 2; mt++)
#pragma unroll
                for (int nt = 0; nt < 4; nt++) {
                    asm volatile(
                        "mma.sync.aligned.m16n8k16.row.col.f32.bf16.bf16.f32 "
                        "{%0,%1,%2,%3}, {%4,%5,%6,%7}, {%8,%9}, {%0,%1,%2,%3};\n"
                        : "+f"(acc[mt][nt][0]), "+f"(acc[mt][nt][1]),
                          "+f"(acc[mt][nt][2]), "+f"(acc[mt][nt][3])
                        : "r"(afr[mt][0]), "r"(afr[mt][1]),
                          "r"(afr[mt][2]), "r"(afr[mt][3]),
                          "r"(bfr[nt >> 1][nt & 1]), "r"(bfr[nt >> 1][2 + (nt & 1)]));
                }
        }
        __syncthreads();
    }

    const int g  = lane >> 2;
    const int t4 = lane & 3;
    // bias only added by the z==0 chunk (partials are summed later)
    const bool addb = (bias != nullptr) && (blockIdx.z == 0);
#pragma unroll
    for (int mt = 0; mt < 2; mt++) {
        int r0 = rowBase + wm * 32 + mt * 16 + g;
#pragma unroll
        for (int nt = 0; nt < 4; nt++) {
            int c0 = colBase + wn * 32 + nt * 8 + t4 * 2;
            float bx = addb ? bias[c0] : 0.f;
            float by = addb ? bias[c0 + 1] : 0.f;
            *(float2*)&Cout[(size_t)r0 * N + c0] =
                make_float2(acc[mt][nt][0] + bx, acc[mt][nt][1] + by);
            *(float2*)&Cout[(size_t)(r0 + 8) * N + c0] =
                make_float2(acc[mt][nt][2] + bx, acc[mt][nt][3] + by);
        }
    }
}

// ---------------------------------------------------------------------------
// 3) BN partial stats over combined h: grid (16, 32); 16 rows x 128 cols
// ---------------------------------------------------------------------------
__global__ void bn_stats_kernel() {
    int col = blockIdx.x * 128 + threadIdx.x;
    int r0  = blockIdx.y * 16;
    float s = 0.f, q = 0.f;
#pragma unroll
    for (int r = 0; r < 16; r++) {
        size_t i = (size_t)(r0 + r) * DIM + col;
        float v = g_hp[i] + g_hp[TWOB * (size_t)DIM + i];
        s += v; q += v * v;
    }
    g_ps[blockIdx.y * DIM + col] = s;
    g_pq[blockIdx.y * DIM + col] = q;
}

// ---------------------------------------------------------------------------
// 4) BN finalize + apply + ReLU -> bf16. grid (8,8): 256 cols x 64 rows
// ---------------------------------------------------------------------------
__global__ void bn_apply_kernel(const float* __restrict__ gamma,
                                const float* __restrict__ beta) {
    int col = blockIdx.x * 256 + threadIdx.x;
    float s = 0.f, q = 0.f;
#pragma unroll
    for (int p = 0; p < 32; p++) {
        s += g_ps[p * DIM + col];
        q += g_pq[p * DIM + col];
    }
    float mu   = s * (1.f / TWOB);
    float var  = q * (1.f / TWOB) - mu * mu;
    float istd = rsqrtf(var + BN_EPS);
    float ga = gamma[col] * istd;
    float be = beta[col] - mu * ga;
    int r0 = blockIdx.y * 64;
#pragma unroll 4
    for (int r = 0; r < 64; r++) {
        size_t i = (size_t)(r0 + r) * DIM + col;
        float v = g_hp[i] + g_hp[TWOB * (size_t)DIM + i];
        g_hb[i] = __float2bfloat16(fmaxf(v * ga + be, 0.f));
    }
}

// ---------------------------------------------------------------------------
// 5) row L2 normalize (combines 2 z partials) -> bf16
// ---------------------------------------------------------------------------
__global__ void rownorm_kernel() {
    __shared__ float red[256];
    int r = blockIdx.x, tid = threadIdx.x;
    const float4* p0 = (const float4*)(g_zp + (size_t)r * DIM);
    const float4* p1 = (const float4*)(g_zp + TWOB * (size_t)DIM + (size_t)r * DIM);
    float4 a0 = p0[tid], a1 = p1[tid];
    float4 b0 = p0[tid + 256], b1 = p1[tid + 256];
    float4 a = make_float4(a0.x + a1.x, a0.y + a1.y, a0.z + a1.z, a0.w + a1.w);
    float4 b = make_float4(b0.x + b1.x, b0.y + b1.y, b0.z + b1.z, b0.w + b1.w);
    float s = a.x * a.x + a.y * a.y + a.z * a.z + a.w * a.w
            + b.x * b.x + b.y * b.y + b.z * b.z + b.w * b.w;
    red[tid] = s;
    __syncthreads();
    for (int o = 128; o > 0; o >>= 1) {
        if (tid < o) red[tid] += red[tid + o];
        __syncthreads();
    }
    float inv = 1.f / fmaxf(sqrtf(red[0]), COS_EPS);
    __nv_bfloat162* dst = (__nv_bfloat162*)(g_znb + (size_t)r * DIM);
    dst[tid * 2]             = __floats2bfloat162_rn(a.x * inv, a.y * inv);
    dst[tid * 2 + 1]         = __floats2bfloat162_rn(a.z * inv, a.w * inv);
    dst[(tid + 256) * 2]     = __floats2bfloat162_rn(b.x * inv, b.y * inv);
    dst[(tid + 256) * 2 + 1] = __floats2bfloat162_rn(b.z * inv, b.w * inv);
}

// ---------------------------------------------------------------------------
// 6) per-row contrastive loss; block i handles sim row i (sums 4 K-partials)
// ---------------------------------------------------------------------------
__global__ void loss_rows_kernel(const int* __restrict__ rel) {
    __shared__ float red[256];
    int i = blockIdx.x, j = threadIdx.x;
    int ri = rel[i];
    int rj = rel[j];
    float s1 = 0.f, s2 = 0.f;
#pragma unroll
    for (int p = 0; p < 4; p++) {
        s1 += g_simp[p * BATCH * TWOB + i * TWOB + j];
        s2 += g_simp[p * BATCH * TWOB + i * TWOB + BATCH + j];
    }
    float e1 = expf(s1 * INV_TEMP);
    float e2 = expf(s2 * INV_TEMP);
    int diff = ri - rj; if (diff < 0) diff = -diff;
    bool isneg = diff > SLICE_RANGE;
    bool ispos = (diff <= SLICE_RANGE) && (j != i);

    red[j] = (isneg ? e1 : 0.f) + e2;
    __syncthreads();
    for (int o = 128; o > 0; o >>= 1) {
        if (j < o) red[j] += red[j + o];
        __syncthreads();
    }
    float neg_sum = red[0];
    __syncthreads();

    red[j] = ispos ? (logf(e1 + neg_sum) - s1 * INV_TEMP) : 0.f;
    __syncthreads();
    for (int o = 128; o > 0; o >>= 1) {
        if (j < o) red[j] += red[j + o];
        __syncthreads();
    }
    float tsum = red[0];
    __syncthreads();

    red[j] = ispos ? 1.f : 0.f;
    __syncthreads();
    for (int o = 128; o > 0; o >>= 1) {
        if (j < o) red[j] += red[j + o];
        __syncthreads();
    }
    if (j == 0) {
        float cnt = red[0];
        g_lossb[i] = tsum / fmaxf(cnt, 1.f);
        g_cntd[i]  = (cnt > 0.f) ? 1.f : 0.f;
    }
}

// ---------------------------------------------------------------------------
// 7) deterministic final reduce -> out[0]=loss, out[1]=n_defined
// ---------------------------------------------------------------------------
__global__ void finalize_kernel(float* __restrict__ out, int out_size) {
    __shared__ float rl[256], rd[256];
    int t = threadIdx.x;
    rl[t] = g_lossb[t] * g_cntd[t];
    rd[t] = g_cntd[t];
    __syncthreads();
    for (int o = 128; o > 0; o >>= 1) {
        if (t < o) { rl[t] += rl[t + o]; rd[t] += rd[t + o]; }
        __syncthreads();
    }
    if (t == 0) {
        out[0] = rl[0];
        if (out_size > 1) out[1] = rd[0];
    }
}

// ---------------------------------------------------------------------------
extern "C" void kernel_launch(void* const* d_in, const int* in_sizes, int n_in,
                              void* d_out, int out_size) {
    const float* z0    = (const float*)d_in[0];
    const float* z1    = (const float*)d_in[1];
    const int*   rel0  = (const int*)d_in[2];
    const float* W1    = (const float*)d_in[4];
    const float* b1    = (const float*)d_in[5];
    const float* gamma = (const float*)d_in[6];
    const float* beta  = (const float*)d_in[7];
    const float* W2    = (const float*)d_in[8];
    const float* b2    = (const float*)d_in[9];

    void *pb_, *w1b_, *w2b_, *hp_, *hb_, *zp_, *znb_, *simp_;
    cudaGetSymbolAddress(&pb_,  g_pb);
    cudaGetSymbolAddress(&w1b_, g_W1b);
    cudaGetSymbolAddress(&w2b_, g_W2b);
    cudaGetSymbolAddress(&hp_,  g_hp);
    cudaGetSymbolAddress(&hb_,  g_hb);
    cudaGetSymbolAddress(&zp_,  g_zp);
    cudaGetSymbolAddress(&znb_, g_znb);
    cudaGetSymbolAddress(&simp_, g_simp);

    // 1) pool + weight conversion
    prep_kernel<<<POOL_BLOCKS + CVT_BLOCKS, 256>>>(z0, z1, W1, W2);
    // 2) GEMM1: h = p @ W1^T + b1, split-K=2 -> 512 CTAs
    gemm_kernel<<<dim3(DIM / 64, TWOB / 64, 2), 128>>>(
        (const bf16*)pb_, (const bf16*)w1b_, (float*)hp_, b1,
        DIM, DIM, DIM / 2, TWOB);
    // 3) BN stats over combined partials (512 blocks)
    bn_stats_kernel<<<dim3(16, 32), 128>>>();
    // 4) BN finalize + apply + ReLU -> bf16
    bn_apply_kernel<<<dim3(8, 8), 256>>>(gamma, beta);
    // 5) GEMM2: z = hb @ W2^T + b2, split-K=2 -> 512 CTAs
    gemm_kernel<<<dim3(DIM / 64, TWOB / 64, 2), 128>>>(
        (const bf16*)hb_, (const bf16*)w2b_, (float*)zp_, b2,
        DIM, DIM, DIM / 2, TWOB);
    // 6) row normalize (combine partials) -> bf16
    rownorm_kernel<<<TWOB, 256>>>();
    // 7) sim partials: 64x64 tiles, split-K=4 -> 128 CTAs
    gemm_kernel<<<dim3(TWOB / 64, BATCH / 64, 4), 128>>>(
        (const bf16*)znb_, (const bf16*)znb_, (float*)simp_, nullptr,
        TWOB, DIM, DIM / 4, BATCH);
    // 8) per-row loss
    loss_rows_kernel<<<BATCH, 256>>>(rel0);
    // 9) deterministic finalize
    finalize_kernel<<<1, 256>>>((float*)d_out, out_size);
}